// round 2
// baseline (speedup 1.0000x reference)
#include <cuda_runtime.h>
#include <math.h>

#define D 512
#define K 5
#define THREADS 256
#define BLOCKS 1184   // 148 SMs * 8

// Precomputed per-launch by prep_kernel (deterministic, allocation-free scratch)
__device__ float g_w[K * D];     // -2 * alpha_d * c_kd
__device__ float g_c2[K];        // sum_d alpha_d * c_kd^2
__device__ float g_sigw[K];      // sigmoid(w_k)

__global__ void prep_kernel(const float* __restrict__ alpha,
                            const float* __restrict__ w,
                            const float* __restrict__ cent)
{
    __shared__ float s_part[K][16];
    const int t = threadIdx.x;          // 512 threads, t = d index
    const float a = alpha[t];
    float part[K];
    #pragma unroll
    for (int k = 0; k < K; k++) {
        const float c = cent[k * D + t];
        g_w[k * D + t] = -2.0f * a * c;
        part[k] = a * c * c;
    }
    const int lane = t & 31, wid = t >> 5;
    #pragma unroll
    for (int k = 0; k < K; k++) {
        #pragma unroll
        for (int off = 16; off > 0; off >>= 1)
            part[k] += __shfl_xor_sync(0xffffffffu, part[k], off);
        if (lane == 0) s_part[k][wid] = part[k];
    }
    __syncthreads();
    if (t < K) {
        float s = 0.0f;
        #pragma unroll
        for (int i = 0; i < 16; i++) s += s_part[t][i];
        g_c2[t] = s;
        g_sigw[t] = 1.0f / (1.0f + __expf(-w[t]));
    }
}

__global__ __launch_bounds__(THREADS, 4) void lfr_main_kernel(
    const float* __restrict__ x,          // (N, D)
    const float* __restrict__ centroids,  // (K, D)
    float* __restrict__ out_map,          // (N, K)
    float* __restrict__ out_rec,          // (N, D)
    float* __restrict__ out_pred,         // (N,)
    int n_rows)
{
    __shared__ float s_w[K * D];      // 10 KB: -2*alpha*c
    __shared__ float s_c[K * D];      // 10 KB: raw centroids (for reconstruction)
    __shared__ float s_c2[K];
    __shared__ float s_sigw[K];

    const int tid = threadIdx.x;
    for (int i = tid; i < K * D; i += THREADS) {
        s_w[i] = g_w[i];
        s_c[i] = centroids[i];
    }
    if (tid < K) { s_c2[tid] = g_c2[tid]; s_sigw[tid] = g_sigw[tid]; }
    __syncthreads();

    const int lane        = tid & 31;
    const int warp_global = (blockIdx.x * THREADS + tid) >> 5;
    const int nwarps      = (BLOCKS * THREADS) >> 5;

    const float4* s_w4 = reinterpret_cast<const float4*>(s_w);
    const float4* s_c4 = reinterpret_cast<const float4*>(s_c);

    for (int row = warp_global; row < n_rows; row += nwarps) {
        const float4* xr = reinterpret_cast<const float4*>(x + (size_t)row * D);

        // Front-batch the 4 coalesced LDG.128s (MLP=4/lane)
        const float4 v0 = xr[lane];
        const float4 v1 = xr[lane + 32];
        const float4 v2 = xr[lane + 64];
        const float4 v3 = xr[lane + 96];

        float dist[K];
        #pragma unroll
        for (int k = 0; k < K; k++) dist[k] = 0.0f;

        #pragma unroll
        for (int j = 0; j < 4; j++) {
            const float4 v = (j == 0) ? v0 : (j == 1) ? v1 : (j == 2) ? v2 : v3;
            const int idx = lane + j * 32;
            #pragma unroll
            for (int k = 0; k < K; k++) {
                const float4 c = s_w4[k * (D / 4) + idx];
                dist[k] += v.x * c.x + v.y * c.y + v.z * c.z + v.w * c.w;
            }
        }

        // Warp tree-reduce the 5 partial dots (replicated in all lanes)
        #pragma unroll
        for (int k = 0; k < K; k++) {
            #pragma unroll
            for (int off = 16; off > 0; off >>= 1)
                dist[k] += __shfl_xor_sync(0xffffffffu, dist[k], off);
            dist[k] += s_c2[k];   // broadcast LDS
        }

        // Softmax over K=5 in registers (replicated per-lane)
        float m = dist[0];
        #pragma unroll
        for (int k = 1; k < K; k++) m = fmaxf(m, dist[k]);
        float mp[K];
        float s = 0.0f;
        #pragma unroll
        for (int k = 0; k < K; k++) { mp[k] = __expf(dist[k] - m); s += mp[k]; }
        const float inv = 1.0f / s;
        #pragma unroll
        for (int k = 0; k < K; k++) mp[k] *= inv;

        // mapping: lanes 0..4 write one value each
        if (lane < K) out_map[(size_t)row * K + lane] = mp[lane];

        // pred: lane 0
        if (lane == 0) {
            float p = 0.0f;
            #pragma unroll
            for (int k = 0; k < K; k++) p += mp[k] * s_sigw[k];
            out_pred[row] = p;
        }

        // reconstructed = mapping @ centroids, each lane writes 16 elems
        float4* orow = reinterpret_cast<float4*>(out_rec + (size_t)row * D);
        #pragma unroll
        for (int j = 0; j < 4; j++) {
            const int idx = lane + j * 32;
            float4 r = make_float4(0.f, 0.f, 0.f, 0.f);
            #pragma unroll
            for (int k = 0; k < K; k++) {
                const float4 c = s_c4[k * (D / 4) + idx];
                r.x += mp[k] * c.x;
                r.y += mp[k] * c.y;
                r.z += mp[k] * c.z;
                r.w += mp[k] * c.w;
            }
            orow[idx] = r;
        }
    }
}

extern "C" void kernel_launch(void* const* d_in, const int* in_sizes, int n_in,
                              void* d_out, int out_size) {
    // metadata order: x, is_protected (unused), alpha_p, classif_w, centroids
    const float* x     = (const float*)d_in[0];
    const float* alpha = (const float*)d_in[2];
    const float* w     = (const float*)d_in[3];
    const float* cent  = (const float*)d_in[4];

    const int n_rows = in_sizes[0] / D;   // 65536

    float* out      = (float*)d_out;
    float* out_map  = out;                              // N*K
    float* out_rec  = out + (size_t)n_rows * K;         // N*D
    float* out_pred = out_rec + (size_t)n_rows * D;     // N

    prep_kernel<<<1, D>>>(alpha, w, cent);
    lfr_main_kernel<<<BLOCKS, THREADS>>>(x, cent, out_map, out_rec, out_pred, n_rows);
}

// round 3
// speedup vs baseline: 1.3020x; 1.3020x over previous
#include <cuda_runtime.h>
#include <math.h>

#define D 512
#define K 5
#define THREADS 256
#define BLOCKS 1184   // 148 SMs * 8

// Precomputed per-launch scratch (allocation-free)
__device__ float g_w[K * D];     // -2 * alpha_d * c_kd
__device__ float g_c2[K];        // sum_d alpha_d * c_kd^2
__device__ float g_sigw[K];      // sigmoid(w_k)

__global__ void prep_kernel(const float* __restrict__ alpha,
                            const float* __restrict__ w,
                            const float* __restrict__ cent)
{
    __shared__ float s_part[K][16];
    const int t = threadIdx.x;          // 512 threads, t = d index
    const float a = alpha[t];
    float part[K];
    #pragma unroll
    for (int k = 0; k < K; k++) {
        const float c = cent[k * D + t];
        g_w[k * D + t] = -2.0f * a * c;
        part[k] = a * c * c;
    }
    const int lane = t & 31, wid = t >> 5;
    #pragma unroll
    for (int k = 0; k < K; k++) {
        #pragma unroll
        for (int off = 16; off > 0; off >>= 1)
            part[k] += __shfl_xor_sync(0xffffffffu, part[k], off);
        if (lane == 0) s_part[k][wid] = part[k];
    }
    __syncthreads();
    if (t < K) {
        float s = 0.0f;
        #pragma unroll
        for (int i = 0; i < 16; i++) s += s_part[t][i];
        g_c2[t] = s;
        g_sigw[t] = 1.0f / (1.0f + __expf(-w[t]));
    }
}

// ---------------------------------------------------------------------------
// Kernel A: distances -> softmax -> mapping + pred. Weights live in registers
// (per-lane d-slice is row-invariant), so the hot loop has ZERO shared-memory
// traffic: 4x LDG.128 + 80 FMA + 25 SHFL per row.
// ---------------------------------------------------------------------------
__global__ __launch_bounds__(THREADS, 2) void map_kernel(
    const float* __restrict__ x,          // (N, D)
    float* __restrict__ out_map,          // (N, K)
    float* __restrict__ out_pred,         // (N,)
    int n_rows)
{
    const int lane = threadIdx.x & 31;

    // Loop-invariant per-lane weight slice: 5k x 4 float4 = 80 regs
    float4 wr[K][4];
    #pragma unroll
    for (int k = 0; k < K; k++) {
        const float4* wk = reinterpret_cast<const float4*>(g_w + k * D);
        #pragma unroll
        for (int j = 0; j < 4; j++) wr[k][j] = wk[lane + j * 32];
    }
    float c2r[K], swr[K];
    #pragma unroll
    for (int k = 0; k < K; k++) { c2r[k] = g_c2[k]; swr[k] = g_sigw[k]; }

    const int warp_global = (blockIdx.x * THREADS + threadIdx.x) >> 5;
    const int nwarps      = (BLOCKS * THREADS) >> 5;

    for (int row = warp_global; row < n_rows; row += nwarps) {
        const float4* xr = reinterpret_cast<const float4*>(x + (size_t)row * D);

        // Front-batch 4 coalesced LDG.128 (MLP=4/lane)
        float4 v[4];
        #pragma unroll
        for (int j = 0; j < 4; j++) v[j] = xr[lane + j * 32];

        float dist[K];
        #pragma unroll
        for (int k = 0; k < K; k++) dist[k] = 0.0f;

        #pragma unroll
        for (int j = 0; j < 4; j++) {
            #pragma unroll
            for (int k = 0; k < K; k++) {
                dist[k] += v[j].x * wr[k][j].x + v[j].y * wr[k][j].y
                         + v[j].z * wr[k][j].z + v[j].w * wr[k][j].w;
            }
        }

        // Warp tree-reduce the 5 partial dots (replicated in all lanes)
        #pragma unroll
        for (int k = 0; k < K; k++) {
            #pragma unroll
            for (int off = 16; off > 0; off >>= 1)
                dist[k] += __shfl_xor_sync(0xffffffffu, dist[k], off);
            dist[k] += c2r[k];
        }

        // Softmax over K=5 in registers
        float m = dist[0];
        #pragma unroll
        for (int k = 1; k < K; k++) m = fmaxf(m, dist[k]);
        float mp[K];
        float s = 0.0f;
        #pragma unroll
        for (int k = 0; k < K; k++) { mp[k] = __expf(dist[k] - m); s += mp[k]; }
        const float inv = 1.0f / s;
        #pragma unroll
        for (int k = 0; k < K; k++) mp[k] *= inv;

        if (lane < K) out_map[(size_t)row * K + lane] = mp[lane];
        if (lane == 0) {
            float p = 0.0f;
            #pragma unroll
            for (int k = 0; k < K; k++) p += mp[k] * swr[k];
            out_pred[row] = p;
        }
    }
}

// ---------------------------------------------------------------------------
// Kernel B: reconstructed = mapping @ centroids. Thread owns a fixed 4-elem
// d-chunk (centroid slice = 20 regs, loop-invariant); mapping reads are
// warp-broadcast L1/L2 hits. Pure write-bound streaming.
// ---------------------------------------------------------------------------
__global__ __launch_bounds__(THREADS) void rec_kernel(
    const float* __restrict__ mapping,    // (N, K)
    const float* __restrict__ centroids,  // (K, D)
    float* __restrict__ out_rec,          // (N, D)
    int n_rows)
{
    const int tid   = blockIdx.x * THREADS + threadIdx.x;
    const int chunk = tid & 127;                 // float4 index within row
    const int row0  = tid >> 7;                  // 2 rows per 256-thr block
    const int rstep = (BLOCKS * THREADS) >> 7;   // rows advanced per sweep

    // Loop-invariant centroid slice: 5 x float4 = 20 regs
    float4 cr[K];
    #pragma unroll
    for (int k = 0; k < K; k++)
        cr[k] = reinterpret_cast<const float4*>(centroids + k * D)[chunk];

    for (int row = row0; row < n_rows; row += rstep) {
        float mp[K];
        #pragma unroll
        for (int k = 0; k < K; k++) mp[k] = __ldg(mapping + (size_t)row * K + k);

        float4 r;
        r.x = mp[0] * cr[0].x; r.y = mp[0] * cr[0].y;
        r.z = mp[0] * cr[0].z; r.w = mp[0] * cr[0].w;
        #pragma unroll
        for (int k = 1; k < K; k++) {
            r.x += mp[k] * cr[k].x;
            r.y += mp[k] * cr[k].y;
            r.z += mp[k] * cr[k].z;
            r.w += mp[k] * cr[k].w;
        }
        reinterpret_cast<float4*>(out_rec + (size_t)row * D)[chunk] = r;
    }
}

extern "C" void kernel_launch(void* const* d_in, const int* in_sizes, int n_in,
                              void* d_out, int out_size) {
    // metadata order: x, is_protected (unused), alpha_p, classif_w, centroids
    const float* x     = (const float*)d_in[0];
    const float* alpha = (const float*)d_in[2];
    const float* w     = (const float*)d_in[3];
    const float* cent  = (const float*)d_in[4];

    const int n_rows = in_sizes[0] / D;   // 65536

    float* out      = (float*)d_out;
    float* out_map  = out;                              // N*K
    float* out_rec  = out + (size_t)n_rows * K;         // N*D
    float* out_pred = out_rec + (size_t)n_rows * D;     // N

    prep_kernel<<<1, D>>>(alpha, w, cent);
    map_kernel<<<BLOCKS, THREADS>>>(x, out_map, out_pred, n_rows);
    rec_kernel<<<BLOCKS, THREADS>>>(out_map, cent, out_rec, n_rows);
}

// round 4
// speedup vs baseline: 1.3031x; 1.0008x over previous
#include <cuda_runtime.h>
#include <math.h>

#define D 512
#define K 5
#define THREADS 256
#define BLOCKS_MAP 296    // persistent: 2 blocks/SM * 148
#define BLOCKS_REC 1184

typedef unsigned long long ull;

__device__ __forceinline__ ull pack2(float lo, float hi) {
    ull r;
    asm("mov.b64 %0, {%1, %2};" : "=l"(r) : "f"(lo), "f"(hi));
    return r;
}
__device__ __forceinline__ void unpack2(ull v, float& lo, float& hi) {
    asm("mov.b64 {%0, %1}, %2;" : "=f"(lo), "=f"(hi) : "l"(v));
}
__device__ __forceinline__ ull fma2(ull a, ull b, ull c) {
    ull d;
    asm("fma.rn.f32x2 %0, %1, %2, %3;" : "=l"(d) : "l"(a), "l"(b), "l"(c));
    return d;
}

// ---------------------------------------------------------------------------
// Kernel A: dist_k = sum_d x_d*(-2 a_d c_kd) + sum_d a_d c_kd^2  -> softmax
// Weight slice lives in registers (row-invariant per lane); c2 partials are
// folded into the per-lane accumulator and summed by the warp reduction.
// Packed f32x2 FMA halves fma-pipe issue. No prep kernel needed.
// ---------------------------------------------------------------------------
__global__ __launch_bounds__(THREADS, 2) void map_kernel(
    const float* __restrict__ x,          // (N, D)
    const float* __restrict__ alpha,      // (D,)
    const float* __restrict__ cw,         // (K,)
    const float* __restrict__ cent,       // (K, D)
    float* __restrict__ out_map,          // (N, K)
    float* __restrict__ out_pred,         // (N,)
    int n_rows)
{
    const int lane = threadIdx.x & 31;

    // ---- per-lane setup (once per persistent block) ----
    float4 a4[4];
    #pragma unroll
    for (int j = 0; j < 4; j++)
        a4[j] = reinterpret_cast<const float4*>(alpha)[lane + j * 32];

    ull  w2[K][8];      // packed -2*alpha*c  (80 regs)
    float pc2[K];       // per-lane partial of sum(alpha*c^2)
    #pragma unroll
    for (int k = 0; k < K; k++) {
        pc2[k] = 0.0f;
        const float4* ck = reinterpret_cast<const float4*>(cent + k * D);
        #pragma unroll
        for (int j = 0; j < 4; j++) {
            const float4 c = ck[lane + j * 32];
            const float wx = -2.0f * a4[j].x * c.x;
            const float wy = -2.0f * a4[j].y * c.y;
            const float wz = -2.0f * a4[j].z * c.z;
            const float ww = -2.0f * a4[j].w * c.w;
            pc2[k] += a4[j].x * c.x * c.x + a4[j].y * c.y * c.y
                    + a4[j].z * c.z * c.z + a4[j].w * c.w * c.w;
            w2[k][2 * j]     = pack2(wx, wy);
            w2[k][2 * j + 1] = pack2(wz, ww);
        }
    }
    float swr[K];
    #pragma unroll
    for (int k = 0; k < K; k++) swr[k] = 1.0f / (1.0f + __expf(-cw[k]));

    const int warp_global = (blockIdx.x * THREADS + threadIdx.x) >> 5;
    const int nwarps      = (BLOCKS_MAP * THREADS) >> 5;

    for (int row = warp_global; row < n_rows; row += nwarps) {
        const float4* xr = reinterpret_cast<const float4*>(x + (size_t)row * D);

        // Front-batch 4 coalesced LDG.128 (MLP=4/lane)
        float4 v[4];
        #pragma unroll
        for (int j = 0; j < 4; j++) v[j] = xr[lane + j * 32];

        ull v2[8];
        #pragma unroll
        for (int j = 0; j < 4; j++) {
            v2[2 * j]     = pack2(v[j].x, v[j].y);
            v2[2 * j + 1] = pack2(v[j].z, v[j].w);
        }

        // Packed dot products: 8 fma2 per k
        ull acc[K];
        #pragma unroll
        for (int k = 0; k < K; k++) acc[k] = pack2(pc2[k], 0.0f);
        #pragma unroll
        for (int p = 0; p < 8; p++) {
            #pragma unroll
            for (int k = 0; k < K; k++)
                acc[k] = fma2(v2[p], w2[k][p], acc[k]);
        }

        float dist[K];
        #pragma unroll
        for (int k = 0; k < K; k++) {
            float lo, hi;
            unpack2(acc[k], lo, hi);
            dist[k] = lo + hi;
        }

        // Warp tree-reduce (replicated); the c2 partials sum to the full c2_k
        #pragma unroll
        for (int k = 0; k < K; k++) {
            #pragma unroll
            for (int off = 16; off > 0; off >>= 1)
                dist[k] += __shfl_xor_sync(0xffffffffu, dist[k], off);
        }

        // Softmax over K=5 in registers
        float m = dist[0];
        #pragma unroll
        for (int k = 1; k < K; k++) m = fmaxf(m, dist[k]);
        float mp[K];
        float s = 0.0f;
        #pragma unroll
        for (int k = 0; k < K; k++) { mp[k] = __expf(dist[k] - m); s += mp[k]; }
        const float inv = 1.0f / s;
        #pragma unroll
        for (int k = 0; k < K; k++) mp[k] *= inv;

        if (lane < K) out_map[(size_t)row * K + lane] = mp[lane];
        if (lane == 0) {
            float p = 0.0f;
            #pragma unroll
            for (int k = 0; k < K; k++) p += mp[k] * swr[k];
            out_pred[row] = p;
        }
    }
}

// ---------------------------------------------------------------------------
// Kernel B: reconstructed = mapping @ centroids. Thread owns a fixed 4-elem
// d-chunk (centroid slice = 20 regs, loop-invariant); write-bound streaming.
// ---------------------------------------------------------------------------
__global__ __launch_bounds__(THREADS) void rec_kernel(
    const float* __restrict__ mapping,    // (N, K)
    const float* __restrict__ centroids,  // (K, D)
    float* __restrict__ out_rec,          // (N, D)
    int n_rows)
{
    const int tid   = blockIdx.x * THREADS + threadIdx.x;
    const int chunk = tid & 127;                     // float4 index within row
    const int row0  = tid >> 7;
    const int rstep = (BLOCKS_REC * THREADS) >> 7;

    float4 cr[K];
    #pragma unroll
    for (int k = 0; k < K; k++)
        cr[k] = reinterpret_cast<const float4*>(centroids + k * D)[chunk];

    for (int row = row0; row < n_rows; row += rstep) {
        float mp[K];
        #pragma unroll
        for (int k = 0; k < K; k++) mp[k] = __ldg(mapping + (size_t)row * K + k);

        float4 r;
        r.x = mp[0] * cr[0].x; r.y = mp[0] * cr[0].y;
        r.z = mp[0] * cr[0].z; r.w = mp[0] * cr[0].w;
        #pragma unroll
        for (int k = 1; k < K; k++) {
            r.x += mp[k] * cr[k].x;
            r.y += mp[k] * cr[k].y;
            r.z += mp[k] * cr[k].z;
            r.w += mp[k] * cr[k].w;
        }
        reinterpret_cast<float4*>(out_rec + (size_t)row * D)[chunk] = r;
    }
}

extern "C" void kernel_launch(void* const* d_in, const int* in_sizes, int n_in,
                              void* d_out, int out_size) {
    // metadata order: x, is_protected (unused), alpha_p, classif_w, centroids
    const float* x     = (const float*)d_in[0];
    const float* alpha = (const float*)d_in[2];
    const float* w     = (const float*)d_in[3];
    const float* cent  = (const float*)d_in[4];

    const int n_rows = in_sizes[0] / D;   // 65536

    float* out      = (float*)d_out;
    float* out_map  = out;                              // N*K
    float* out_rec  = out + (size_t)n_rows * K;         // N*D
    float* out_pred = out_rec + (size_t)n_rows * D;     // N

    map_kernel<<<BLOCKS_MAP, THREADS>>>(x, alpha, w, cent, out_map, out_pred, n_rows);
    rec_kernel<<<BLOCKS_REC, THREADS>>>(out_map, cent, out_rec, n_rows);
}

// round 6
// speedup vs baseline: 1.4174x; 1.0877x over previous
#include <cuda_runtime.h>
#include <math.h>

#define D 512
#define K 5
#define THREADS 256
#define BLOCKS_MAP 296    // 2 blocks/SM * 148
#define BLOCKS_REC 1024   // rows/thread = 65536 / (1024*256/128) = 32 exactly

typedef unsigned long long ull;

__device__ __forceinline__ ull pack2(float lo, float hi) {
    ull r;
    asm("mov.b64 %0, {%1, %2};" : "=l"(r) : "f"(lo), "f"(hi));
    return r;
}
__device__ __forceinline__ void unpack2(ull v, float& lo, float& hi) {
    asm("mov.b64 {%0, %1}, %2;" : "=f"(lo), "=f"(hi) : "l"(v));
}
__device__ __forceinline__ ull fma2(ull a, ull b, ull c) {
    ull d;
    asm("fma.rn.f32x2 %0, %1, %2, %3;" : "=l"(d) : "l"(a), "l"(b), "l"(c));
    return d;
}

// ---------------------------------------------------------------------------
// Kernel A: dist_k = x . (-2 a c_k) + sum(a c_k^2) -> softmax -> mapping,pred
// Weights in registers (row-invariant per lane). Software-pipelined: next
// row's loads issue right after the fma stage consumes the current row, so
// the DRAM round-trip overlaps the shuffle/softmax/store tail.
//
// ull layout within a row: float4 chunk j (float4 idx lane+32j) maps to
//   v2[2j]   = xr[2*lane + 64j]     (x,y)
//   v2[2j+1] = xr[2*lane + 64j + 1] (z,w)
// i.e. v2[p] = xr[2*lane + 64*(p>>1) + (p&1)], matching w2[k][p].
// ---------------------------------------------------------------------------
__global__ __launch_bounds__(THREADS, 2) void map_kernel(
    const float* __restrict__ x,          // (N, D)
    const float* __restrict__ alpha,      // (D,)
    const float* __restrict__ cw,         // (K,)
    const float* __restrict__ cent,       // (K, D)
    float* __restrict__ out_map,          // (N, K)
    float* __restrict__ out_pred,         // (N,)
    int n_rows)
{
    const int lane = threadIdx.x & 31;

    // ---- per-lane setup (once) ----
    ull  w2[K][8];      // packed -2*alpha*c  (80 regs)
    float pc2[K];       // per-lane partial of sum(alpha*c^2)
    {
        float4 a4[4];
        #pragma unroll
        for (int j = 0; j < 4; j++)
            a4[j] = reinterpret_cast<const float4*>(alpha)[lane + j * 32];
        #pragma unroll
        for (int k = 0; k < K; k++) {
            pc2[k] = 0.0f;
            const float4* ck = reinterpret_cast<const float4*>(cent + k * D);
            #pragma unroll
            for (int j = 0; j < 4; j++) {
                const float4 c = ck[lane + j * 32];
                pc2[k] += a4[j].x * c.x * c.x + a4[j].y * c.y * c.y
                        + a4[j].z * c.z * c.z + a4[j].w * c.w * c.w;
                w2[k][2 * j]     = pack2(-2.0f * a4[j].x * c.x, -2.0f * a4[j].y * c.y);
                w2[k][2 * j + 1] = pack2(-2.0f * a4[j].z * c.z, -2.0f * a4[j].w * c.w);
            }
        }
    }
    float swr[K];
    #pragma unroll
    for (int k = 0; k < K; k++) swr[k] = 1.0f / (1.0f + __expf(-cw[k]));

    const int warp_global = (blockIdx.x * THREADS + threadIdx.x) >> 5;
    const int nwarps      = (BLOCKS_MAP * THREADS) >> 5;

    // Prime the pipeline
    ull v2[8];
    int row = warp_global;
    if (row < n_rows) {
        const ull* xr = reinterpret_cast<const ull*>(x + (size_t)row * D);
        #pragma unroll
        for (int p = 0; p < 8; p++) v2[p] = xr[2 * lane + ((p >> 1) << 6) + (p & 1)];
    }

    for (; row < n_rows; ) {
        // ---- fma stage: consume v2 (40 FFMA2) ----
        ull acc[K];
        #pragma unroll
        for (int k = 0; k < K; k++) acc[k] = pack2(pc2[k], 0.0f);
        #pragma unroll
        for (int p = 0; p < 8; p++) {
            #pragma unroll
            for (int k = 0; k < K; k++)
                acc[k] = fma2(v2[p], w2[k][p], acc[k]);
        }

        // ---- prefetch next row (overlaps the reduction/softmax below) ----
        const int nrow = row + nwarps;
        if (nrow < n_rows) {
            const ull* xr = reinterpret_cast<const ull*>(x + (size_t)nrow * D);
            #pragma unroll
            for (int p = 0; p < 8; p++) v2[p] = xr[2 * lane + ((p >> 1) << 6) + (p & 1)];
        }

        float dist[K];
        #pragma unroll
        for (int k = 0; k < K; k++) {
            float lo, hi;
            unpack2(acc[k], lo, hi);
            dist[k] = lo + hi;
        }

        // Warp tree-reduce (c2 partials sum to the full c2_k)
        #pragma unroll
        for (int k = 0; k < K; k++) {
            #pragma unroll
            for (int off = 16; off > 0; off >>= 1)
                dist[k] += __shfl_xor_sync(0xffffffffu, dist[k], off);
        }

        // Softmax over K=5
        float m = dist[0];
        #pragma unroll
        for (int k = 1; k < K; k++) m = fmaxf(m, dist[k]);
        float mp[K];
        float s = 0.0f;
        #pragma unroll
        for (int k = 0; k < K; k++) { mp[k] = __expf(dist[k] - m); s += mp[k]; }
        const float inv = 1.0f / s;
        #pragma unroll
        for (int k = 0; k < K; k++) mp[k] *= inv;

        if (lane < K) out_map[(size_t)row * K + lane] = mp[lane];
        if (lane == 0) {
            float p = 0.0f;
            #pragma unroll
            for (int k = 0; k < K; k++) p += mp[k] * swr[k];
            out_pred[row] = p;
        }
        row = nrow;
    }
}

// ---------------------------------------------------------------------------
// Kernel B: reconstructed = mapping @ centroids. Thread owns a fixed float4
// d-chunk (centroid slice = 20 regs). Unrolled 4 rows: 20 batched mapping
// LDGs then 4 independent STG.128 -> high MLP, write-bound streaming.
// ---------------------------------------------------------------------------
__global__ __launch_bounds__(THREADS) void rec_kernel(
    const float* __restrict__ mapping,    // (N, K)
    const float* __restrict__ centroids,  // (K, D)
    float* __restrict__ out_rec,          // (N, D)
    int n_rows)
{
    const int tid   = blockIdx.x * THREADS + threadIdx.x;
    const int chunk = tid & 127;                     // float4 index within row
    const int row0  = tid >> 7;                      // in [0, 2048)
    const int rstep = (BLOCKS_REC * THREADS) >> 7;   // 2048

    float4 cr[K];
    #pragma unroll
    for (int k = 0; k < K; k++)
        cr[k] = reinterpret_cast<const float4*>(centroids + k * D)[chunk];

    // 65536 = 32 * 2048 -> exactly 8 outer iterations of 4 rows each
    for (int r = row0; r < n_rows; r += 4 * rstep) {
        float mp[4][K];
        #pragma unroll
        for (int i = 0; i < 4; i++) {
            const float* mrow = mapping + (size_t)(r + i * rstep) * K;
            #pragma unroll
            for (int k = 0; k < K; k++) mp[i][k] = __ldg(mrow + k);
        }
        #pragma unroll
        for (int i = 0; i < 4; i++) {
            float4 o;
            o.x = mp[i][0] * cr[0].x; o.y = mp[i][0] * cr[0].y;
            o.z = mp[i][0] * cr[0].z; o.w = mp[i][0] * cr[0].w;
            #pragma unroll
            for (int k = 1; k < K; k++) {
                o.x += mp[i][k] * cr[k].x;
                o.y += mp[i][k] * cr[k].y;
                o.z += mp[i][k] * cr[k].z;
                o.w += mp[i][k] * cr[k].w;
            }
            reinterpret_cast<float4*>(out_rec + (size_t)(r + i * rstep) * D)[chunk] = o;
        }
    }
}

extern "C" void kernel_launch(void* const* d_in, const int* in_sizes, int n_in,
                              void* d_out, int out_size) {
    // metadata order: x, is_protected (unused), alpha_p, classif_w, centroids
    const float* x     = (const float*)d_in[0];
    const float* alpha = (const float*)d_in[2];
    const float* w     = (const float*)d_in[3];
    const float* cent  = (const float*)d_in[4];

    const int n_rows = in_sizes[0] / D;   // 65536

    float* out      = (float*)d_out;
    float* out_map  = out;                              // N*K
    float* out_rec  = out + (size_t)n_rows * K;         // N*D
    float* out_pred = out_rec + (size_t)n_rows * D;     // N

    map_kernel<<<BLOCKS_MAP, THREADS>>>(x, alpha, w, cent, out_map, out_pred, n_rows);
    rec_kernel<<<BLOCKS_REC, THREADS>>>(out_map, cent, out_rec, n_rows);
}

// round 7
// speedup vs baseline: 2.0203x; 1.4254x over previous
#include <cuda_runtime.h>
#include <math.h>

#define D 512
#define K 5
#define THREADS 256
#define BLOCKS 296    // persistent: 2 blocks/SM * 148

typedef unsigned long long ull;

__device__ __forceinline__ ull pack2(float lo, float hi) {
    ull r;
    asm("mov.b64 %0, {%1, %2};" : "=l"(r) : "f"(lo), "f"(hi));
    return r;
}
__device__ __forceinline__ void unpack2(ull v, float& lo, float& hi) {
    asm("mov.b64 {%0, %1}, %2;" : "=f"(lo), "=f"(hi) : "l"(v));
}
__device__ __forceinline__ ull fma2(ull a, ull b, ull c) {
    ull d;
    asm("fma.rn.f32x2 %0, %1, %2, %3;" : "=l"(d) : "l"(a), "l"(b), "l"(c));
    return d;
}
__device__ __forceinline__ ull mul2(ull a, ull b) {
    ull d;
    asm("mul.rn.f32x2 %0, %1, %2;" : "=l"(d) : "l"(a), "l"(b));
    return d;
}

// ---------------------------------------------------------------------------
// Fully fused kernel. Per warp-row:
//   dist_k  = x . w_k + pc2_k  (w = -2*alpha*c in regs, softmax-invariant
//             |alpha*x^2| term dropped)        -> warp-reduce -> softmax
//   rec_d   = rinv_d * sum_k mp_k * w_kd       (rinv = -0.5/alpha, shared)
//   pred    = sum_k mp_k * sigmoid(cw_k)
// Next row's x is prefetched right after the dist-fma stage, so the whole
// reduce/softmax/reconstruction tail runs under the DRAM round-trip.
//
// ull layout within a row: float4 chunk j (float4 idx lane+32j):
//   v2[2j]   = xr[2*lane + 64j]     (x,y)
//   v2[2j+1] = xr[2*lane + 64j + 1] (z,w)
// ---------------------------------------------------------------------------
__global__ __launch_bounds__(THREADS, 2) void lfr_fused(
    const float* __restrict__ x,          // (N, D)
    const float* __restrict__ alpha,      // (D,)
    const float* __restrict__ cw,         // (K,)
    const float* __restrict__ cent,       // (K, D)
    float* __restrict__ out_map,          // (N, K)
    float* __restrict__ out_rec,          // (N, D)
    float* __restrict__ out_pred,         // (N,)
    int n_rows)
{
    __shared__ float s_rinv[D];           // -0.5 / alpha_d
    __shared__ float s_swr[K];            // sigmoid(cw_k)

    const int tid  = threadIdx.x;
    const int lane = tid & 31;

    for (int i = tid; i < D; i += THREADS) s_rinv[i] = -0.5f / alpha[i];
    if (tid < K) s_swr[tid] = 1.0f / (1.0f + __expf(-cw[tid]));

    // ---- per-lane invariant setup: packed weights + c2 partials ----
    ull  w2[K][8];      // packed -2*alpha*c  (80 regs)
    float pc2[K];       // per-lane partial of sum(alpha*c^2)
    {
        float4 a4[4];
        #pragma unroll
        for (int j = 0; j < 4; j++)
            a4[j] = reinterpret_cast<const float4*>(alpha)[lane + j * 32];
        #pragma unroll
        for (int k = 0; k < K; k++) {
            pc2[k] = 0.0f;
            const float4* ck = reinterpret_cast<const float4*>(cent + k * D);
            #pragma unroll
            for (int j = 0; j < 4; j++) {
                const float4 c = ck[lane + j * 32];
                pc2[k] += a4[j].x * c.x * c.x + a4[j].y * c.y * c.y
                        + a4[j].z * c.z * c.z + a4[j].w * c.w * c.w;
                w2[k][2 * j]     = pack2(-2.0f * a4[j].x * c.x, -2.0f * a4[j].y * c.y);
                w2[k][2 * j + 1] = pack2(-2.0f * a4[j].z * c.z, -2.0f * a4[j].w * c.w);
            }
        }
    }
    __syncthreads();

    const int warp_global = (blockIdx.x * THREADS + tid) >> 5;
    const int nwarps      = (BLOCKS * THREADS) >> 5;

    // Prime the pipeline
    ull v2[8];
    int row = warp_global;
    if (row < n_rows) {
        const ull* xr = reinterpret_cast<const ull*>(x + (size_t)row * D);
        #pragma unroll
        for (int p = 0; p < 8; p++) v2[p] = xr[2 * lane + ((p >> 1) << 6) + (p & 1)];
    }

    while (row < n_rows) {
        // ---- distance fma stage: consume v2 (40 FFMA2) ----
        ull acc[K];
        #pragma unroll
        for (int k = 0; k < K; k++) acc[k] = pack2(pc2[k], 0.0f);
        #pragma unroll
        for (int p = 0; p < 8; p++) {
            #pragma unroll
            for (int k = 0; k < K; k++)
                acc[k] = fma2(v2[p], w2[k][p], acc[k]);
        }

        // ---- prefetch next row: everything below runs under this latency ----
        const int nrow = row + nwarps;
        if (nrow < n_rows) {
            const ull* xr = reinterpret_cast<const ull*>(x + (size_t)nrow * D);
            #pragma unroll
            for (int p = 0; p < 8; p++) v2[p] = xr[2 * lane + ((p >> 1) << 6) + (p & 1)];
        }

        float dist[K];
        #pragma unroll
        for (int k = 0; k < K; k++) {
            float lo, hi;
            unpack2(acc[k], lo, hi);
            dist[k] = lo + hi;
        }

        // Warp tree-reduce (pc2 partials sum to full c2_k)
        #pragma unroll
        for (int k = 0; k < K; k++) {
            #pragma unroll
            for (int off = 16; off > 0; off >>= 1)
                dist[k] += __shfl_xor_sync(0xffffffffu, dist[k], off);
        }

        // Softmax over K=5 (replicated in all lanes)
        float m = dist[0];
        #pragma unroll
        for (int k = 1; k < K; k++) m = fmaxf(m, dist[k]);
        float mp[K];
        float s = 0.0f;
        #pragma unroll
        for (int k = 0; k < K; k++) { mp[k] = __expf(dist[k] - m); s += mp[k]; }
        const float inv = 1.0f / s;
        #pragma unroll
        for (int k = 0; k < K; k++) mp[k] *= inv;

        if (lane < K) out_map[(size_t)row * K + lane] = mp[lane];
        if (lane == 0) {
            float p = 0.0f;
            #pragma unroll
            for (int k = 0; k < K; k++) p += mp[k] * s_swr[k];
            out_pred[row] = p;
        }

        // ---- reconstruction: rec_d = rinv_d * sum_k mp_k * w_kd ----
        ull mp2[K];
        #pragma unroll
        for (int k = 0; k < K; k++) mp2[k] = pack2(mp[k], mp[k]);

        float4* orow = reinterpret_cast<float4*>(out_rec + (size_t)row * D);
        const float4* rinv4 = reinterpret_cast<const float4*>(s_rinv);
        #pragma unroll
        for (int j = 0; j < 4; j++) {
            ull sa = mul2(mp2[0], w2[0][2 * j]);
            ull sb = mul2(mp2[0], w2[0][2 * j + 1]);
            #pragma unroll
            for (int k = 1; k < K; k++) {
                sa = fma2(mp2[k], w2[k][2 * j], sa);
                sb = fma2(mp2[k], w2[k][2 * j + 1], sb);
            }
            const float4 rv = rinv4[lane + j * 32];
            float4 o;
            float t0, t1;
            unpack2(sa, t0, t1);
            o.x = t0 * rv.x; o.y = t1 * rv.y;
            unpack2(sb, t0, t1);
            o.z = t0 * rv.z; o.w = t1 * rv.w;
            orow[lane + j * 32] = o;
        }

        row = nrow;
    }
}

extern "C" void kernel_launch(void* const* d_in, const int* in_sizes, int n_in,
                              void* d_out, int out_size) {
    // metadata order: x, is_protected (unused), alpha_p, classif_w, centroids
    const float* x     = (const float*)d_in[0];
    const float* alpha = (const float*)d_in[2];
    const float* w     = (const float*)d_in[3];
    const float* cent  = (const float*)d_in[4];

    const int n_rows = in_sizes[0] / D;   // 65536

    float* out      = (float*)d_out;
    float* out_map  = out;                              // N*K
    float* out_rec  = out + (size_t)n_rows * K;         // N*D
    float* out_pred = out_rec + (size_t)n_rows * D;     // N

    lfr_fused<<<BLOCKS, THREADS>>>(x, alpha, w, cent, out_map, out_rec, out_pred, n_rows);
}